// round 6
// baseline (speedup 1.0000x reference)
#include <cuda_runtime.h>
#include <math.h>

#define BATCH 8
#define SEQ   2048
#define DIM   256
#define ROWS  (BATCH*SEQ)          // 16384
#define LOG2E 1.4426950408889634f

// ---------------- scratch (static device globals; no allocation) ----------------
__device__ float g_WT[4*DIM*DIM];   // transposed weights: [d][e] for Wq,Wk,Wv,Wo
__device__ float g_Q[ROWS*DIM];
__device__ float g_K[ROWS*DIM];
__device__ float g_V[ROWS*DIM];
__device__ float g_loc[ROWS*DIM];

__device__ __forceinline__ float fexp2(float x) {
    float y; asm("ex2.approx.ftz.f32 %0, %1;" : "=f"(y) : "f"(x)); return y;
}

#define FMA4(o,a,b) do{ (o).x = fmaf((a),(b).x,(o).x); (o).y = fmaf((a),(b).y,(o).y); \
                        (o).z = fmaf((a),(b).z,(o).z); (o).w = fmaf((a),(b).w,(o).w);}while(0)

// ---------------- weight transpose (tiny; runs once per launch) ----------------
__global__ void transpose_w_kernel(const float* __restrict__ Wq, const float* __restrict__ Wk,
                                   const float* __restrict__ Wv, const float* __restrict__ Wo) {
    const float* W = (blockIdx.x==0)?Wq:((blockIdx.x==1)?Wk:((blockIdx.x==2)?Wv:Wo));
    float* WT = g_WT + (size_t)blockIdx.x*DIM*DIM;
    for (int idx = threadIdx.x; idx < DIM*DIM; idx += blockDim.x) {
        int d = idx >> 8, e = idx & 255;
        WT[idx] = W[e*DIM + d];          // WT[d][e] = W[e][d]
    }
}

// ---------------- shared 64x256 GEMM mainloop:  acc += A[r0:r0+64, :] * WT ----------------
// thread map: tx = tid&15, ty = tid>>4 ; rows 4*ty+i ; cols 4*tx + 64*j + comp
__device__ __forceinline__ void gemm64x256(const float* __restrict__ A, int r0,
                                           const float* __restrict__ WT,
                                           float* Xs /*64x33*/, float* WsT /*32x256*/,
                                           int tx, int ty, int tid, float4 acc[4][4]) {
    for (int dc = 0; dc < 8; ++dc) {
        // stage A tile [64 x 32] (padded rows of 33 to kill bank conflicts on a-loads)
        #pragma unroll
        for (int it = 0; it < 2; ++it) {
            int idx = tid + it*256;          // 0..511
            int r = idx >> 3, d4 = idx & 7;
            float4 v = *(const float4*)(A + (size_t)(r0+r)*DIM + dc*32 + d4*4);
            float* p = &Xs[r*33 + d4*4];
            p[0]=v.x; p[1]=v.y; p[2]=v.z; p[3]=v.w;
        }
        // stage WT chunk [32 x 256] (direct coalesced float4 copy)
        #pragma unroll
        for (int it = 0; it < 8; ++it) {
            int idx = tid + it*256;          // 0..2047
            int dd = idx >> 6, c4 = idx & 63;
            *(float4*)&WsT[dd*256 + c4*4] =
                *(const float4*)(WT + (size_t)(dc*32+dd)*DIM + c4*4);
        }
        __syncthreads();
        #pragma unroll 8
        for (int dd = 0; dd < 32; ++dd) {
            float a[4];
            #pragma unroll
            for (int i = 0; i < 4; ++i) a[i] = Xs[(4*ty+i)*33 + dd];
            #pragma unroll
            for (int j = 0; j < 4; ++j) {
                float4 b = *(float4*)&WsT[dd*256 + 4*tx + 64*j];
                #pragma unroll
                for (int i = 0; i < 4; ++i) FMA4(acc[i][j], a[i], b);
            }
        }
        __syncthreads();
    }
}

// ---------------- QKV projections ----------------
__global__ __launch_bounds__(256) void qkv_kernel(const float* __restrict__ x,
        const float* __restrict__ bq, const float* __restrict__ bk, const float* __restrict__ bv) {
    __shared__ float Xs[64*33];
    __shared__ float WsT[32*256];
    int m = blockIdx.y;
    const float* WT   = g_WT + (size_t)m*DIM*DIM;
    const float* bias = (m==0)?bq:((m==1)?bk:bv);
    float*       outp = (m==0)?g_Q:((m==1)?g_K:g_V);
    int r0 = blockIdx.x*64;
    int tid = threadIdx.x, tx = tid&15, ty = tid>>4;

    float4 acc[4][4];
    #pragma unroll
    for (int i=0;i<4;i++)
        #pragma unroll
        for (int j=0;j<4;j++) acc[i][j] = make_float4(0.f,0.f,0.f,0.f);

    gemm64x256(x, r0, WT, Xs, WsT, tx, ty, tid, acc);

    #pragma unroll
    for (int j=0;j<4;j++){
        float4 bb = *(const float4*)(bias + 4*tx + 64*j);
        #pragma unroll
        for (int i=0;i<4;i++){
            float4 v = acc[i][j];
            v.x+=bb.x; v.y+=bb.y; v.z+=bb.z; v.w+=bb.w;
            *(float4*)(outp + (size_t)(r0+4*ty+i)*DIM + 4*tx + 64*j) = v;
        }
    }
}

// ---------------- fp32 flash attention: 64 queries x 128-key tiles ----------------
// smem: Qs[64][257] | KsT[32][132] | Vs[32][256] | Ps[64][132]   = 149248 B
#define SMEM_ATTN ((64*257 + 32*132 + 32*256 + 64*132) * (int)sizeof(float))

__global__ __launch_bounds__(256) void attn_kernel() {
    extern __shared__ float sm[];
    float* Qs  = sm;                 // 64*257
    float* KsT = Qs  + 64*257;       // 32*132
    float* Vs  = KsT + 32*132;       // 32*256
    float* Ps  = Vs  + 32*256;       // 64*132
    int b  = blockIdx.y;
    int q0 = blockIdx.x*64;
    int tid = threadIdx.x, tx = tid&15, ty = tid>>4;
    const float* Qg = g_Q + (size_t)b*SEQ*DIM;
    const float* Kg = g_K + (size_t)b*SEQ*DIM;
    const float* Vg = g_V + (size_t)b*SEQ*DIM;

    // stage full Q tile [64 x 256] once (row pad 257 -> conflict-free broadcast a-loads)
    #pragma unroll
    for (int it=0; it<16; ++it) {
        int idx = tid + it*256;
        int r = idx >> 6, d4 = idx & 63;
        float4 v = *(const float4*)(Qg + (size_t)(q0+r)*DIM + d4*4);
        float* p = &Qs[r*257 + d4*4];
        p[0]=v.x; p[1]=v.y; p[2]=v.z; p[3]=v.w;
    }
    // (first __syncthreads inside the kt loop orders this before any Qs read)

    float4 o[4][4];
    #pragma unroll
    for (int i=0;i<4;i++)
        #pragma unroll
        for (int j=0;j<4;j++) o[i][j] = make_float4(0.f,0.f,0.f,0.f);
    float mrow[4] = {-INFINITY,-INFINITY,-INFINITY,-INFINITY};
    float lrow[4] = {0.f,0.f,0.f,0.f};

    for (int kt = 0; kt < SEQ/128; ++kt) {
        int k0 = kt*128;
        // ---- S = Q * K^T  (64 x 128), per-thread s[row i][col 4*tx+64*jj+ii] ----
        float s[4][8];
        #pragma unroll
        for (int i=0;i<4;i++)
            #pragma unroll
            for (int c=0;c<8;c++) s[i][c] = 0.f;

        for (int dc = 0; dc < 8; ++dc) {
            // stage transposed K chunk [32 d][128 c] (pad 132)
            #pragma unroll
            for (int it=0; it<4; ++it) {
                int idx = tid + it*256;        // 0..1023
                int c = idx >> 3, d4 = idx & 7;
                float4 v = *(const float4*)(Kg + (size_t)(k0+c)*DIM + dc*32 + d4*4);
                KsT[(d4*4+0)*132 + c] = v.x;
                KsT[(d4*4+1)*132 + c] = v.y;
                KsT[(d4*4+2)*132 + c] = v.z;
                KsT[(d4*4+3)*132 + c] = v.w;
            }
            __syncthreads();
            #pragma unroll 8
            for (int dd = 0; dd < 32; ++dd) {
                float a[4];
                #pragma unroll
                for (int i=0;i<4;i++) a[i] = Qs[(4*ty+i)*257 + dc*32 + dd];
                float4 b0 = *(float4*)&KsT[dd*132 + 4*tx];
                float4 b1 = *(float4*)&KsT[dd*132 + 4*tx + 64];
                #pragma unroll
                for (int i=0;i<4;i++){
                    s[i][0] = fmaf(a[i], b0.x, s[i][0]);
                    s[i][1] = fmaf(a[i], b0.y, s[i][1]);
                    s[i][2] = fmaf(a[i], b0.z, s[i][2]);
                    s[i][3] = fmaf(a[i], b0.w, s[i][3]);
                    s[i][4] = fmaf(a[i], b1.x, s[i][4]);
                    s[i][5] = fmaf(a[i], b1.y, s[i][5]);
                    s[i][6] = fmaf(a[i], b1.z, s[i][6]);
                    s[i][7] = fmaf(a[i], b1.w, s[i][7]);
                }
            }
            __syncthreads();
        }

        // ---- online softmax (row spread across the 16 tx lanes of each half-warp) ----
        #pragma unroll
        for (int i=0;i<4;i++){
            float mx = s[i][0];
            #pragma unroll
            for (int c=1;c<8;c++) mx = fmaxf(mx, s[i][c]);
            #pragma unroll
            for (int off=8; off>=1; off>>=1)
                mx = fmaxf(mx, __shfl_xor_sync(0xffffffffu, mx, off));
            float mnew = fmaxf(mrow[i], mx);
            float corr = fexp2((mrow[i]-mnew)*LOG2E);   // 0 on first tile (m=-inf)
            mrow[i] = mnew;
            float ps = 0.f;
            #pragma unroll
            for (int c=0;c<8;c++){
                float p = fexp2((s[i][c]-mnew)*LOG2E);
                s[i][c] = p; ps += p;
            }
            #pragma unroll
            for (int off=8; off>=1; off>>=1)
                ps += __shfl_xor_sync(0xffffffffu, ps, off);
            lrow[i] = lrow[i]*corr + ps;
            #pragma unroll
            for (int j=0;j<4;j++){
                o[i][j].x*=corr; o[i][j].y*=corr; o[i][j].z*=corr; o[i][j].w*=corr;
            }
            #pragma unroll
            for (int jj=0; jj<2; ++jj)
                #pragma unroll
                for (int ii=0; ii<4; ++ii)
                    Ps[(4*ty+i)*132 + 4*tx + 64*jj + ii] = s[i][jj*4+ii];
        }
        __syncthreads();

        // ---- O += P * V  (accumulate over 128 keys, V staged in 32-key chunks) ----
        for (int vc = 0; vc < 4; ++vc) {
            #pragma unroll
            for (int it=0; it<8; ++it) {
                int idx = tid + it*256;        // 0..2047
                int k = idx >> 6, c4 = idx & 63;
                *(float4*)&Vs[k*256 + c4*4] =
                    *(const float4*)(Vg + (size_t)(k0+vc*32+k)*DIM + c4*4);
            }
            __syncthreads();
            #pragma unroll 8
            for (int kk=0; kk<32; ++kk){
                float a[4];
                #pragma unroll
                for (int i=0;i<4;i++) a[i] = Ps[(4*ty+i)*132 + vc*32 + kk];
                #pragma unroll
                for (int j=0;j<4;j++){
                    float4 bv4 = *(float4*)&Vs[kk*256 + 4*tx + 64*j];
                    #pragma unroll
                    for (int i=0;i<4;i++) FMA4(o[i][j], a[i], bv4);
                }
            }
            __syncthreads();
        }
    }

    // finalize: divide by row sums, write loc
    float* locp = g_loc + (size_t)b*SEQ*DIM;
    #pragma unroll
    for (int i=0;i<4;i++){
        float inv = 1.0f / lrow[i];
        #pragma unroll
        for (int j=0;j<4;j++){
            float4 v = o[i][j];
            v.x*=inv; v.y*=inv; v.z*=inv; v.w*=inv;
            *(float4*)(locp + (size_t)(q0+4*ty+i)*DIM + 4*tx + 64*j) = v;
        }
    }
}

// ---------------- output projection + LayerNorm + LeakyReLU ----------------
__global__ __launch_bounds__(256) void proj_ln_kernel(const float* __restrict__ bo,
        const float* __restrict__ gamma, const float* __restrict__ beta,
        float* __restrict__ out) {
    __shared__ float Xs[64*33];
    __shared__ float WsT[32*256];
    const float* WT = g_WT + (size_t)3*DIM*DIM;
    int r0 = blockIdx.x*64;
    int tid = threadIdx.x, tx = tid&15, ty = tid>>4;

    float4 acc[4][4];
    #pragma unroll
    for (int i=0;i<4;i++)
        #pragma unroll
        for (int j=0;j<4;j++) acc[i][j] = make_float4(0.f,0.f,0.f,0.f);

    gemm64x256(g_loc, r0, WT, Xs, WsT, tx, ty, tid, acc);

    // + bias
    #pragma unroll
    for (int j=0;j<4;j++){
        float4 bb = *(const float4*)(bo + 4*tx + 64*j);
        #pragma unroll
        for (int i=0;i<4;i++){
            acc[i][j].x+=bb.x; acc[i][j].y+=bb.y; acc[i][j].z+=bb.z; acc[i][j].w+=bb.w;
        }
    }

    // LayerNorm per row (row = 4*ty+i, 16 cols per lane, reduce over 16 tx lanes)
    #pragma unroll
    for (int i=0;i<4;i++){
        float ssum = 0.f;
        #pragma unroll
        for (int j=0;j<4;j++) ssum += acc[i][j].x + acc[i][j].y + acc[i][j].z + acc[i][j].w;
        #pragma unroll
        for (int off=8; off>=1; off>>=1) ssum += __shfl_xor_sync(0xffffffffu, ssum, off);
        float mu = ssum * (1.0f/DIM);

        float vsum = 0.f;
        #pragma unroll
        for (int j=0;j<4;j++){
            float dx = acc[i][j].x-mu, dy = acc[i][j].y-mu, dz = acc[i][j].z-mu, dw = acc[i][j].w-mu;
            vsum += dx*dx + dy*dy + dz*dz + dw*dw;
        }
        #pragma unroll
        for (int off=8; off>=1; off>>=1) vsum += __shfl_xor_sync(0xffffffffu, vsum, off);
        float rstd = rsqrtf(vsum*(1.0f/DIM) + 1e-5f);

        #pragma unroll
        for (int j=0;j<4;j++){
            float4 g  = *(const float4*)(gamma + 4*tx + 64*j);
            float4 bt = *(const float4*)(beta  + 4*tx + 64*j);
            float4 h  = acc[i][j];
            float4 y;
            y.x = (h.x-mu)*rstd*g.x + bt.x;  y.x = (y.x>=0.f) ? y.x : 0.01f*y.x;
            y.y = (h.y-mu)*rstd*g.y + bt.y;  y.y = (y.y>=0.f) ? y.y : 0.01f*y.y;
            y.z = (h.z-mu)*rstd*g.z + bt.z;  y.z = (y.z>=0.f) ? y.z : 0.01f*y.z;
            y.w = (h.w-mu)*rstd*g.w + bt.w;  y.w = (y.w>=0.f) ? y.w : 0.01f*y.w;
            *(float4*)(out + (size_t)(r0+4*ty+i)*DIM + 4*tx + 64*j) = y;
        }
    }
}

// ---------------- entry point ----------------
extern "C" void kernel_launch(void* const* d_in, const int* in_sizes, int n_in,
                              void* d_out, int out_size) {
    const float* x     = (const float*)d_in[0];
    const float* Wq    = (const float*)d_in[1];
    const float* bq    = (const float*)d_in[2];
    const float* Wk    = (const float*)d_in[3];
    const float* bk    = (const float*)d_in[4];
    const float* Wv    = (const float*)d_in[5];
    const float* bv    = (const float*)d_in[6];
    const float* Wo    = (const float*)d_in[7];
    const float* bo    = (const float*)d_in[8];
    const float* gamma = (const float*)d_in[9];
    const float* beta  = (const float*)d_in[10];
    float* out = (float*)d_out;

    cudaFuncSetAttribute(attn_kernel, cudaFuncAttributeMaxDynamicSharedMemorySize, SMEM_ATTN);

    transpose_w_kernel<<<4, 256>>>(Wq, Wk, Wv, Wo);
    qkv_kernel<<<dim3(ROWS/64, 3), 256>>>(x, bq, bk, bv);
    attn_kernel<<<dim3(SEQ/64, BATCH), 256, SMEM_ATTN>>>();
    proj_ln_kernel<<<ROWS/64, 256>>>(bo, gamma, beta, out);
}

// round 7
// speedup vs baseline: 1.0003x; 1.0003x over previous
#include <cuda_runtime.h>
#include <math.h>

#define BATCH 8
#define SEQ   2048
#define DIM   256
#define ROWS  (BATCH*SEQ)          // 16384
#define LOG2E 1.4426950408889634f

// ---------------- scratch (static device globals; no allocation) ----------------
__device__ float g_WT[4*DIM*DIM];   // transposed weights: [d][e] for Wq,Wk,Wv,Wo
__device__ float g_Q[ROWS*DIM];
__device__ float g_K[ROWS*DIM];
__device__ float g_V[ROWS*DIM];
__device__ float g_loc[ROWS*DIM];

__device__ __forceinline__ float fexp2(float x) {
    float y; asm("ex2.approx.ftz.f32 %0, %1;" : "=f"(y) : "f"(x)); return y;
}

#define FMA4(o,a,b) do{ (o).x = fmaf((a),(b).x,(o).x); (o).y = fmaf((a),(b).y,(o).y); \
                        (o).z = fmaf((a),(b).z,(o).z); (o).w = fmaf((a),(b).w,(o).w);}while(0)

// ---------------- weight transpose (tiny; runs once per launch) ----------------
__global__ void transpose_w_kernel(const float* __restrict__ Wq, const float* __restrict__ Wk,
                                   const float* __restrict__ Wv, const float* __restrict__ Wo) {
    const float* W = (blockIdx.x==0)?Wq:((blockIdx.x==1)?Wk:((blockIdx.x==2)?Wv:Wo));
    float* WT = g_WT + (size_t)blockIdx.x*DIM*DIM;
    for (int idx = threadIdx.x; idx < DIM*DIM; idx += blockDim.x) {
        int d = idx >> 8, e = idx & 255;
        WT[idx] = W[e*DIM + d];          // WT[d][e] = W[e][d]
    }
}

// ---------------- shared 64x256 GEMM mainloop:  acc += A[r0:r0+64, :] * WT ----------------
// thread map: tx = tid&15, ty = tid>>4 ; rows 4*ty+i ; cols 4*tx + 64*j + comp
__device__ __forceinline__ void gemm64x256(const float* __restrict__ A, int r0,
                                           const float* __restrict__ WT,
                                           float* Xs /*64x33*/, float* WsT /*32x256*/,
                                           int tx, int ty, int tid, float4 acc[4][4]) {
    for (int dc = 0; dc < 8; ++dc) {
        // stage A tile [64 x 32] (padded rows of 33 to kill bank conflicts on a-loads)
        #pragma unroll
        for (int it = 0; it < 2; ++it) {
            int idx = tid + it*256;          // 0..511
            int r = idx >> 3, d4 = idx & 7;
            float4 v = *(const float4*)(A + (size_t)(r0+r)*DIM + dc*32 + d4*4);
            float* p = &Xs[r*33 + d4*4];
            p[0]=v.x; p[1]=v.y; p[2]=v.z; p[3]=v.w;
        }
        // stage WT chunk [32 x 256] (direct coalesced float4 copy)
        #pragma unroll
        for (int it = 0; it < 8; ++it) {
            int idx = tid + it*256;          // 0..2047
            int dd = idx >> 6, c4 = idx & 63;
            *(float4*)&WsT[dd*256 + c4*4] =
                *(const float4*)(WT + (size_t)(dc*32+dd)*DIM + c4*4);
        }
        __syncthreads();
        #pragma unroll 8
        for (int dd = 0; dd < 32; ++dd) {
            float a[4];
            #pragma unroll
            for (int i = 0; i < 4; ++i) a[i] = Xs[(4*ty+i)*33 + dd];
            #pragma unroll
            for (int j = 0; j < 4; ++j) {
                float4 b = *(float4*)&WsT[dd*256 + 4*tx + 64*j];
                #pragma unroll
                for (int i = 0; i < 4; ++i) FMA4(acc[i][j], a[i], b);
            }
        }
        __syncthreads();
    }
}

// ---------------- QKV projections ----------------
__global__ __launch_bounds__(256) void qkv_kernel(const float* __restrict__ x,
        const float* __restrict__ bq, const float* __restrict__ bk, const float* __restrict__ bv) {
    __shared__ float Xs[64*33];
    __shared__ float WsT[32*256];
    int m = blockIdx.y;
    const float* WT   = g_WT + (size_t)m*DIM*DIM;
    const float* bias = (m==0)?bq:((m==1)?bk:bv);
    float*       outp = (m==0)?g_Q:((m==1)?g_K:g_V);
    int r0 = blockIdx.x*64;
    int tid = threadIdx.x, tx = tid&15, ty = tid>>4;

    float4 acc[4][4];
    #pragma unroll
    for (int i=0;i<4;i++)
        #pragma unroll
        for (int j=0;j<4;j++) acc[i][j] = make_float4(0.f,0.f,0.f,0.f);

    gemm64x256(x, r0, WT, Xs, WsT, tx, ty, tid, acc);

    #pragma unroll
    for (int j=0;j<4;j++){
        float4 bb = *(const float4*)(bias + 4*tx + 64*j);
        #pragma unroll
        for (int i=0;i<4;i++){
            float4 v = acc[i][j];
            v.x+=bb.x; v.y+=bb.y; v.z+=bb.z; v.w+=bb.w;
            *(float4*)(outp + (size_t)(r0+4*ty+i)*DIM + 4*tx + 64*j) = v;
        }
    }
}

// ---------------- fp32 flash attention: 64 queries x 128-key tiles ----------------
// smem: Qs[64][257] | KsT[32][132] | Vs[32][256] | Ps[64][132]   = 149248 B
#define SMEM_ATTN ((64*257 + 32*132 + 32*256 + 64*132) * (int)sizeof(float))

__global__ __launch_bounds__(256) void attn_kernel() {
    extern __shared__ float sm[];
    float* Qs  = sm;                 // 64*257
    float* KsT = Qs  + 64*257;       // 32*132
    float* Vs  = KsT + 32*132;       // 32*256
    float* Ps  = Vs  + 32*256;       // 64*132
    int b  = blockIdx.y;
    int q0 = blockIdx.x*64;
    int tid = threadIdx.x, tx = tid&15, ty = tid>>4;
    const float* Qg = g_Q + (size_t)b*SEQ*DIM;
    const float* Kg = g_K + (size_t)b*SEQ*DIM;
    const float* Vg = g_V + (size_t)b*SEQ*DIM;

    // stage full Q tile [64 x 256] once (row pad 257 -> conflict-free broadcast a-loads)
    #pragma unroll
    for (int it=0; it<16; ++it) {
        int idx = tid + it*256;
        int r = idx >> 6, d4 = idx & 63;
        float4 v = *(const float4*)(Qg + (size_t)(q0+r)*DIM + d4*4);
        float* p = &Qs[r*257 + d4*4];
        p[0]=v.x; p[1]=v.y; p[2]=v.z; p[3]=v.w;
    }
    // (first __syncthreads inside the kt loop orders this before any Qs read)

    float4 o[4][4];
    #pragma unroll
    for (int i=0;i<4;i++)
        #pragma unroll
        for (int j=0;j<4;j++) o[i][j] = make_float4(0.f,0.f,0.f,0.f);
    float mrow[4] = {-INFINITY,-INFINITY,-INFINITY,-INFINITY};
    float lrow[4] = {0.f,0.f,0.f,0.f};

    for (int kt = 0; kt < SEQ/128; ++kt) {
        int k0 = kt*128;
        // ---- S = Q * K^T  (64 x 128), per-thread s[row i][col 4*tx+64*jj+ii] ----
        float s[4][8];
        #pragma unroll
        for (int i=0;i<4;i++)
            #pragma unroll
            for (int c=0;c<8;c++) s[i][c] = 0.f;

        for (int dc = 0; dc < 8; ++dc) {
            // stage transposed K chunk [32 d][128 c] (pad 132)
            #pragma unroll
            for (int it=0; it<4; ++it) {
                int idx = tid + it*256;        // 0..1023
                int c = idx >> 3, d4 = idx & 7;
                float4 v = *(const float4*)(Kg + (size_t)(k0+c)*DIM + dc*32 + d4*4);
                KsT[(d4*4+0)*132 + c] = v.x;
                KsT[(d4*4+1)*132 + c] = v.y;
                KsT[(d4*4+2)*132 + c] = v.z;
                KsT[(d4*4+3)*132 + c] = v.w;
            }
            __syncthreads();
            #pragma unroll 8
            for (int dd = 0; dd < 32; ++dd) {
                float a[4];
                #pragma unroll
                for (int i=0;i<4;i++) a[i] = Qs[(4*ty+i)*257 + dc*32 + dd];
                float4 b0 = *(float4*)&KsT[dd*132 + 4*tx];
                float4 b1 = *(float4*)&KsT[dd*132 + 4*tx + 64];
                #pragma unroll
                for (int i=0;i<4;i++){
                    s[i][0] = fmaf(a[i], b0.x, s[i][0]);
                    s[i][1] = fmaf(a[i], b0.y, s[i][1]);
                    s[i][2] = fmaf(a[i], b0.z, s[i][2]);
                    s[i][3] = fmaf(a[i], b0.w, s[i][3]);
                    s[i][4] = fmaf(a[i], b1.x, s[i][4]);
                    s[i][5] = fmaf(a[i], b1.y, s[i][5]);
                    s[i][6] = fmaf(a[i], b1.z, s[i][6]);
                    s[i][7] = fmaf(a[i], b1.w, s[i][7]);
                }
            }
            __syncthreads();
        }

        // ---- online softmax (row spread across the 16 tx lanes of each half-warp) ----
        #pragma unroll
        for (int i=0;i<4;i++){
            float mx = s[i][0];
            #pragma unroll
            for (int c=1;c<8;c++) mx = fmaxf(mx, s[i][c]);
            #pragma unroll
            for (int off=8; off>=1; off>>=1)
                mx = fmaxf(mx, __shfl_xor_sync(0xffffffffu, mx, off));
            float mnew = fmaxf(mrow[i], mx);
            float corr = fexp2((mrow[i]-mnew)*LOG2E);   // 0 on first tile (m=-inf)
            mrow[i] = mnew;
            float ps = 0.f;
            #pragma unroll
            for (int c=0;c<8;c++){
                float p = fexp2((s[i][c]-mnew)*LOG2E);
                s[i][c] = p; ps += p;
            }
            #pragma unroll
            for (int off=8; off>=1; off>>=1)
                ps += __shfl_xor_sync(0xffffffffu, ps, off);
            lrow[i] = lrow[i]*corr + ps;
            #pragma unroll
            for (int j=0;j<4;j++){
                o[i][j].x*=corr; o[i][j].y*=corr; o[i][j].z*=corr; o[i][j].w*=corr;
            }
            #pragma unroll
            for (int jj=0; jj<2; ++jj)
                #pragma unroll
                for (int ii=0; ii<4; ++ii)
                    Ps[(4*ty+i)*132 + 4*tx + 64*jj + ii] = s[i][jj*4+ii];
        }
        __syncthreads();

        // ---- O += P * V  (accumulate over 128 keys, V staged in 32-key chunks) ----
        for (int vc = 0; vc < 4; ++vc) {
            #pragma unroll
            for (int it=0; it<8; ++it) {
                int idx = tid + it*256;        // 0..2047
                int k = idx >> 6, c4 = idx & 63;
                *(float4*)&Vs[k*256 + c4*4] =
                    *(const float4*)(Vg + (size_t)(k0+vc*32+k)*DIM + c4*4);
            }
            __syncthreads();
            #pragma unroll 8
            for (int kk=0; kk<32; ++kk){
                float a[4];
                #pragma unroll
                for (int i=0;i<4;i++) a[i] = Ps[(4*ty+i)*132 + vc*32 + kk];
                #pragma unroll
                for (int j=0;j<4;j++){
                    float4 bv4 = *(float4*)&Vs[kk*256 + 4*tx + 64*j];
                    #pragma unroll
                    for (int i=0;i<4;i++) FMA4(o[i][j], a[i], bv4);
                }
            }
            __syncthreads();
        }
    }

    // finalize: divide by row sums, write loc
    float* locp = g_loc + (size_t)b*SEQ*DIM;
    #pragma unroll
    for (int i=0;i<4;i++){
        float inv = 1.0f / lrow[i];
        #pragma unroll
        for (int j=0;j<4;j++){
            float4 v = o[i][j];
            v.x*=inv; v.y*=inv; v.z*=inv; v.w*=inv;
            *(float4*)(locp + (size_t)(q0+4*ty+i)*DIM + 4*tx + 64*j) = v;
        }
    }
}

// ---------------- output projection + LayerNorm + LeakyReLU ----------------
__global__ __launch_bounds__(256) void proj_ln_kernel(const float* __restrict__ bo,
        const float* __restrict__ gamma, const float* __restrict__ beta,
        float* __restrict__ out) {
    __shared__ float Xs[64*33];
    __shared__ float WsT[32*256];
    const float* WT = g_WT + (size_t)3*DIM*DIM;
    int r0 = blockIdx.x*64;
    int tid = threadIdx.x, tx = tid&15, ty = tid>>4;

    float4 acc[4][4];
    #pragma unroll
    for (int i=0;i<4;i++)
        #pragma unroll
        for (int j=0;j<4;j++) acc[i][j] = make_float4(0.f,0.f,0.f,0.f);

    gemm64x256(g_loc, r0, WT, Xs, WsT, tx, ty, tid, acc);

    // + bias
    #pragma unroll
    for (int j=0;j<4;j++){
        float4 bb = *(const float4*)(bo + 4*tx + 64*j);
        #pragma unroll
        for (int i=0;i<4;i++){
            acc[i][j].x+=bb.x; acc[i][j].y+=bb.y; acc[i][j].z+=bb.z; acc[i][j].w+=bb.w;
        }
    }

    // LayerNorm per row (row = 4*ty+i, 16 cols per lane, reduce over 16 tx lanes)
    #pragma unroll
    for (int i=0;i<4;i++){
        float ssum = 0.f;
        #pragma unroll
        for (int j=0;j<4;j++) ssum += acc[i][j].x + acc[i][j].y + acc[i][j].z + acc[i][j].w;
        #pragma unroll
        for (int off=8; off>=1; off>>=1) ssum += __shfl_xor_sync(0xffffffffu, ssum, off);
        float mu = ssum * (1.0f/DIM);

        float vsum = 0.f;
        #pragma unroll
        for (int j=0;j<4;j++){
            float dx = acc[i][j].x-mu, dy = acc[i][j].y-mu, dz = acc[i][j].z-mu, dw = acc[i][j].w-mu;
            vsum += dx*dx + dy*dy + dz*dz + dw*dw;
        }
        #pragma unroll
        for (int off=8; off>=1; off>>=1) vsum += __shfl_xor_sync(0xffffffffu, vsum, off);
        float rstd = rsqrtf(vsum*(1.0f/DIM) + 1e-5f);

        #pragma unroll
        for (int j=0;j<4;j++){
            float4 g  = *(const float4*)(gamma + 4*tx + 64*j);
            float4 bt = *(const float4*)(beta  + 4*tx + 64*j);
            float4 h  = acc[i][j];
            float4 y;
            y.x = (h.x-mu)*rstd*g.x + bt.x;  y.x = (y.x>=0.f) ? y.x : 0.01f*y.x;
            y.y = (h.y-mu)*rstd*g.y + bt.y;  y.y = (y.y>=0.f) ? y.y : 0.01f*y.y;
            y.z = (h.z-mu)*rstd*g.z + bt.z;  y.z = (y.z>=0.f) ? y.z : 0.01f*y.z;
            y.w = (h.w-mu)*rstd*g.w + bt.w;  y.w = (y.w>=0.f) ? y.w : 0.01f*y.w;
            *(float4*)(out + (size_t)(r0+4*ty+i)*DIM + 4*tx + 64*j) = y;
        }
    }
}

// ---------------- entry point ----------------
extern "C" void kernel_launch(void* const* d_in, const int* in_sizes, int n_in,
                              void* d_out, int out_size) {
    const float* x     = (const float*)d_in[0];
    const float* Wq    = (const float*)d_in[1];
    const float* bq    = (const float*)d_in[2];
    const float* Wk    = (const float*)d_in[3];
    const float* bk    = (const float*)d_in[4];
    const float* Wv    = (const float*)d_in[5];
    const float* bv    = (const float*)d_in[6];
    const float* Wo    = (const float*)d_in[7];
    const float* bo    = (const float*)d_in[8];
    const float* gamma = (const float*)d_in[9];
    const float* beta  = (const float*)d_in[10];
    float* out = (float*)d_out;

    cudaFuncSetAttribute(attn_kernel, cudaFuncAttributeMaxDynamicSharedMemorySize, SMEM_ATTN);

    transpose_w_kernel<<<4, 256>>>(Wq, Wk, Wv, Wo);
    qkv_kernel<<<dim3(ROWS/64, 3), 256>>>(x, bq, bk, bv);
    attn_kernel<<<dim3(SEQ/64, BATCH), 256, SMEM_ATTN>>>();
    proj_ln_kernel<<<ROWS/64, 256>>>(bo, gamma, beta, out);
}